// round 13
// baseline (speedup 1.0000x reference)
#include <cuda_runtime.h>
#include <math.h>

#define BATCH 4
#define NQ    300
#define NC    80
#define NK    17
#define HW    4096
#define NWORDS 10                      // ceil(300/32)
#define BN    (BATCH*NQ)
#define TB    256
#define NSLICES (BATCH*NQ*NK)          // 20400
#define ARGB  588                      // persistent argmax blocks
#define GRID_TOTAL (BATCH + ARGB)      // 592 = 148 SMs * 4 blocks -> ONE wave
#define EPI   32                       // epilogue blocks

#define NEGV (-1000000000.0f)
#define IOU_THR   0.7f
#define SCORE_THR 0.01f

typedef unsigned long long u64;
typedef unsigned int u32;

// scratch
__device__ u64   g_key[NSLICES];       // sortable (value, ~idx) key per slice
__device__ int   g_sel[BN];            // selected original query per slot
__device__ int   g_done  = 0;
__device__ int   g_done2 = 0;

// ---- shared buffer layout (NMS branch only) ----
#define OFF_MASK   0          // u32 [NQ][NWORDS]  = 12000 B
#define OFF_OBOX   12000      // float4[NQ]        = 4800
#define OFF_BX1    16800
#define OFF_BY1    18000
#define OFF_BX2    19200
#define OFF_BY2    20400
#define OFF_OAREA  21600
#define OFF_SCORE  22800
#define OFF_SKEY   24000      // 16B aligned
#define OFF_LABEL  25200
#define OFF_ORDER  26400
#define OFF_VALIDA 27600
#define OFF_VS     27900
#define OFF_RED    28208      // float[32] / keepw u32[10]
#define OFF_MISC   28336      // s_maxc
#define SBUF_SIZE  28352

// monotone map: float bits -> u32 preserving IEEE order (non-NaN)
__device__ __forceinline__ u32 fmap(float f) {
    u32 u = __float_as_uint(f);
    return u ^ ((u32)(((int)u) >> 31) | 0x80000000u);
}
// sortable key: high 32 = mapped value, low 32 = ~idx (max => min idx on tie)
__device__ __forceinline__ u64 mkkey(float f, int idx) {
    return ((u64)fmap(f) << 32) | (u32)(~idx);
}
__device__ __forceinline__ u64 kmax(u64 a, u64 b) { return a > b ? a : b; }

// fold one float4 with element base index bi into a key
__device__ __forceinline__ u64 fold4k(float4 v, int bi) {
    u64 a = kmax(mkkey(v.x, bi),     mkkey(v.y, bi + 1));
    u64 b = kmax(mkkey(v.z, bi + 2), mkkey(v.w, bi + 3));
    return kmax(a, b);
}

__global__ void __launch_bounds__(TB, 4)
fused_kernel(const float* __restrict__ logits,
             const float* __restrict__ boxes,
             const float* __restrict__ sizes,
             const float* __restrict__ hm,
             const float* __restrict__ off,
             float* __restrict__ out) {
    __shared__ __align__(16) unsigned char sbuf[SBUF_SIZE];
    __shared__ int s_rank;
    const int tid = threadIdx.x;

    if (blockIdx.x >= BATCH) {
        // ---- barrier-free warp-autonomous argmax (RED.MAX.U64 combine) -----
        const int a = blockIdx.x - BATCH;
        const int lane = tid & 31;
        const float4* hm4 = reinterpret_cast<const float4*>(hm);

        int s = a;
        // buffer A: slice s
        float4 a0, a1, a2, a3;
        {
            const float4* p = hm4 + (size_t)s * (HW / 4);
            a0 = p[tid]; a1 = p[tid + 256]; a2 = p[tid + 512]; a3 = p[tid + 768];
        }

        while (s < NSLICES) {
            // issue next slice's loads (clamped: unconditional => no spill)
            const int s1 = s + ARGB;
            const int s1c = (s1 < NSLICES) ? s1 : (NSLICES - 1);
            float4 b0, b1, b2, b3;
            {
                const float4* p = hm4 + (size_t)s1c * (HW / 4);
                b0 = p[tid]; b1 = p[tid + 256]; b2 = p[tid + 512]; b3 = p[tid + 768];
            }

            // fold 16 elements of slice s into one sortable key (tree)
            u64 k = kmax(kmax(fold4k(a0, tid * 4),
                              fold4k(a1, (tid + 256) * 4)),
                         kmax(fold4k(a2, (tid + 512) * 4),
                              fold4k(a3, (tid + 768) * 4)));
            // warp max-reduce (value max, lowest idx on ties via ~idx)
#pragma unroll
            for (int o = 16; o > 0; o >>= 1)
                k = kmax(k, __shfl_xor_sync(0xFFFFFFFFu, k, o));
            if (lane == 0) atomicMax(&g_key[s], k);   // RED, fire-and-forget

            a0 = b0; a1 = b1; a2 = b2; a3 = b3;
            s = s1;
        }
    } else {
        // ---------------- NMS core: one block per batch ----------------------
        const int b = blockIdx.x;
        unsigned int* mask = (unsigned int*)(sbuf + OFF_MASK);   // [NQ][NWORDS]
        float4* obox  = (float4*)(sbuf + OFF_OBOX);
        float* bx1    = (float*)(sbuf + OFF_BX1);
        float* by1    = (float*)(sbuf + OFF_BY1);
        float* bx2    = (float*)(sbuf + OFF_BX2);
        float* by2    = (float*)(sbuf + OFF_BY2);
        float* oarea  = (float*)(sbuf + OFF_OAREA);
        float* score  = (float*)(sbuf + OFF_SCORE);
        float* skey   = (float*)(sbuf + OFF_SKEY);
        int*   label  = (int*)(sbuf + OFF_LABEL);
        int*   order  = (int*)(sbuf + OFF_ORDER);
        unsigned char* validA = (unsigned char*)(sbuf + OFF_VALIDA);
        unsigned char* vs     = (unsigned char*)(sbuf + OFF_VS);
        float* red    = (float*)(sbuf + OFF_RED);
        unsigned int* keepw = (unsigned int*)(sbuf + OFF_RED);   // reused
        float* s_maxc = (float*)(sbuf + OFF_MISC);

        const float s0 = sizes[b * 2 + 0];
        const float s1 = sizes[b * 2 + 1];

        // --- abs boxes + score/label ---
        float lmax = 0.0f;
        for (int n = tid; n < NQ; n += TB) {
            const float* pb = boxes + ((size_t)b * NQ + n) * 4;
            float cx = pb[0], cy = pb[1], w = pb[2], h = pb[3];
            float x1 = (cx - w / 2.0f) * s0;
            float y1 = (cy - h / 2.0f) * s1;
            float x2 = (cx + w / 2.0f) * s0;
            float y2 = (cy + h / 2.0f) * s1;
            bx1[n] = x1; by1[n] = y1; bx2[n] = x2; by2[n] = y2;
            lmax = fmaxf(lmax, fmaxf(fmaxf(fabsf(x1), fabsf(y1)),
                                     fmaxf(fabsf(x2), fabsf(y2))));
            const float4* pl4 = reinterpret_cast<const float4*>(
                logits + ((size_t)b * NQ + n) * NC);
            float bestv = -INFINITY;
            int   bl = 0;
#pragma unroll 4
            for (int c4 = 0; c4 < NC / 4; c4++) {
                float4 v = pl4[c4];
                int c = c4 * 4;
                if (v.x > bestv) { bestv = v.x; bl = c; }
                if (v.y > bestv) { bestv = v.y; bl = c + 1; }
                if (v.z > bestv) { bestv = v.z; bl = c + 2; }
                if (v.w > bestv) { bestv = v.w; bl = c + 3; }
            }
            float sc = 1.0f / (1.0f + expf(-bestv));
            score[n]  = sc;
            label[n]  = bl;
            bool valid = sc > SCORE_THR;
            validA[n] = valid ? 1 : 0;
            skey[n]   = valid ? sc : NEGV;
        }
#pragma unroll
        for (int o = 16; o > 0; o >>= 1)
            lmax = fmaxf(lmax, __shfl_down_sync(0xFFFFFFFFu, lmax, o));
        if ((tid & 31) == 0) red[tid >> 5] = lmax;
        __syncthreads();
        if (tid == 0) {
            float m = red[0];
#pragma unroll
            for (int w = 1; w < 8; w++) m = fmaxf(m, red[w]);
            *s_maxc = m + 1.0f;
        }
        __syncthreads();
        const float maxc = *s_maxc;

        // --- stable descending rank sort (== jnp.argsort(-s)) ---
        for (int i = tid; i < NQ; i += TB) {
            float si = skey[i];
            int r = 0;
            const float4* sk4 = reinterpret_cast<const float4*>(skey);
#pragma unroll 5
            for (int j4 = 0; j4 < NQ / 4; j4++) {
                float4 v = sk4[j4];
                int j = j4 * 4;
                r += (v.x > si) || (v.x == si && (j    ) < i);
                r += (v.y > si) || (v.y == si && (j + 1) < i);
                r += (v.z > si) || (v.z == si && (j + 2) < i);
                r += (v.w > si) || (v.w == si && (j + 3) < i);
            }
            order[r] = i;
        }
        __syncthreads();

        // --- sorted class-offset boxes ---
        for (int r = tid; r < NQ; r += TB) {
            int i = order[r];
            float o = (float)label[i] * maxc;
            float x1 = bx1[i] + o, y1 = by1[i] + o;
            float x2 = bx2[i] + o, y2 = by2[i] + o;
            obox[r] = make_float4(x1, y1, x2, y2);
            oarea[r] = (x2 - x1) * (y2 - y1);
            vs[r] = validA[i];
        }
        __syncthreads();

        // --- IoU bitmask, w-major: warp lanes share w -> broadcast LDS ---
        for (int u = tid; u < NQ * NWORDS; u += TB) {
            int i = u % NQ;
            int w = u / NQ;
            int j0 = w * 32;
            unsigned int bits = 0;
            if (j0 + 31 > i) {
                float4 bi4 = obox[i];
                float ai = oarea[i];
                int jend = (NQ - j0 < 32) ? (NQ - j0) : 32;
                for (int jj = 0; jj < jend; jj++) {
                    int j = j0 + jj;
                    if (j > i) {
                        float4 bj = obox[j];
                        float iw = fmaxf(fminf(bi4.z, bj.z) - fmaxf(bi4.x, bj.x), 0.0f);
                        float ih = fmaxf(fminf(bi4.w, bj.w) - fmaxf(bi4.y, bj.y), 0.0f);
                        float inter = iw * ih;
                        if (inter > 0.0f) {        // inter==0 -> iou==0 (exact)
                            float iou = inter / (ai + oarea[j] - inter + 1e-9f);
                            if (iou > IOU_THR) bits |= (1u << jj);
                        }
                    }
                }
            }
            mask[i * NWORDS + w] = bits;
        }
        __syncthreads();

        // --- greedy pass: warp 0, lane w owns suppression word w ---
        if (tid < 32) {
            const int lane = tid;
            unsigned int supp_w = 0, kw_w = 0;
            for (int i = 0; i < NQ; i++) {
                unsigned int sw = __shfl_sync(0xFFFFFFFFu, supp_w, i >> 5);
                unsigned int k = (unsigned int)vs[i] & (((sw >> (i & 31)) & 1u) ^ 1u);
                if (lane == (i >> 5)) kw_w |= k << (i & 31);
                unsigned int m = 0u - k;
                if (lane < NWORDS) supp_w |= mask[i * NWORDS + lane] & m;
            }
            if (lane < NWORDS) keepw[lane] = kw_w;
        }
        __syncthreads();

        // --- stable partition via popcount + write fl/fb/fs/vk, stash g_sel ---
        const int base = b * NQ;
        float* fl = out;
        float* fb = out + BN;
        float* fs = out + BN * 5;
        float* vk = out + BN * 6 + BN * NK * 3;

        for (int r = tid; r < NQ; r += TB) {
            int wq = r >> 5, bq = r & 31;
            int kb = 0, nk = 0;
#pragma unroll
            for (int w = 0; w < NWORDS; w++) {
                unsigned int kwv = keepw[w];
                nk += __popc(kwv);
                if (w < wq)  kb += __popc(kwv);
                if (w == wq) kb += __popc(kwv & ((1u << bq) - 1u));
            }
            bool kf = (keepw[wq] >> bq) & 1u;
            int m = kf ? kb : (nk + (r - kb));
            int q = order[r];
            g_sel[base + m] = q;
            vk[base + m] = kf ? 1.0f : 0.0f;
            fl[base + m] = kf ? (float)label[q] : -1.0f;
            fs[base + m] = kf ? score[q] : 0.0f;
            float* pb = fb + (size_t)(base + m) * 4;
            pb[0] = kf ? bx1[q] : 0.0f;
            pb[1] = kf ? by1[q] : 0.0f;
            pb[2] = kf ? bx2[q] : 0.0f;
            pb[3] = kf ? by2[q] : 0.0f;
        }
    }

    // ------------- distributed last-EPI-blocks epilogue: keypoint gather -----
    __threadfence();
    __syncthreads();
    if (tid == 0) s_rank = atomicAdd(&g_done, 1);
    __syncthreads();
    const int rank = s_rank;
    if (rank >= GRID_TOTAL - EPI) {
        if (tid == 0) {
            while (atomicAdd(&g_done, 0) < GRID_TOTAL) {}
        }
        __syncthreads();
        __threadfence();
        float* ak = out + BN * 6;
        const float* vk = out + BN * 6 + BN * NK * 3;
        const float* fb = out + BN;
        const float2* off2 = reinterpret_cast<const float2*>(off);
        const int er = rank - (GRID_TOTAL - EPI);
        for (int idx = er * TB + tid; idx < NSLICES; idx += EPI * TB) {
            int k  = idx % NK;
            int bm = idx / NK;                 // b*NQ + m
            float* o = ak + (size_t)idx * 3;
            if (vk[bm] != 0.0f) {
                int bq = bm / NQ;
                int q = g_sel[bm];
                const int slice = (bq * NQ + q) * NK + k;
                u64 key = g_key[slice];
                int bi = (int)(~((u32)key)) & (HW - 1);
                u32 mapped = (u32)(key >> 32);
                u32 ubits = (mapped & 0x80000000u) ? (mapped ^ 0x80000000u)
                                                   : ~mapped;
                float M = __uint_as_float(ubits);
                float2 ov = off2[slice];
                float nx = (float)(bi & 63) / 63.0f + ov.x;
                float ny = (float)(bi >> 6) / 63.0f + ov.y;
                nx = fminf(fmaxf(nx, 0.0f), 1.0f);
                ny = fminf(fmaxf(ny, 0.0f), 1.0f);
                const float* pb = fb + (size_t)bm * 4;
                float x1 = pb[0], y1 = pb[1], x2 = pb[2], y2 = pb[3];
                o[0] = x1 + nx * (x2 - x1);
                o[1] = y1 + ny * (y2 - y1);
                o[2] = M;
            } else {
                o[0] = 0.0f; o[1] = 0.0f; o[2] = 0.0f;
            }
        }
        __threadfence();
        __syncthreads();
        if (tid == 0) {
            int o2 = atomicAdd(&g_done2, 1);
            if (o2 == EPI - 1) { g_done = 0; g_done2 = 0; }   // reset for replay
        }
    }
}

// ---------------------------------------------------------------------------
extern "C" void kernel_launch(void* const* d_in, const int* in_sizes, int n_in,
                              void* d_out, int out_size) {
    const float* logits = (const float*)d_in[0];   // (4,300,80)
    const float* boxes  = (const float*)d_in[1];   // (4,300,4)
    const float* hm     = (const float*)d_in[2];   // (4,300,17,64,64)
    const float* off    = (const float*)d_in[3];   // (4,300,17,2)
    const float* sizes  = (const float*)d_in[4];   // (4,2)
    float* out = (float*)d_out;

    fused_kernel<<<GRID_TOTAL, TB>>>(logits, boxes, sizes, hm, off, out);
}

// round 14
// speedup vs baseline: 1.0206x; 1.0206x over previous
#include <cuda_runtime.h>
#include <math.h>

#define BATCH 4
#define NQ    300
#define NC    80
#define NK    17
#define HW    4096
#define NWORDS 10                      // ceil(300/32)
#define BN    (BATCH*NQ)
#define TB    256
#define NSLICES (BATCH*NQ*NK)          // 20400
#define ARGB  588                      // persistent argmax blocks
#define GRID_TOTAL (BATCH + ARGB)      // 592 = 148 SMs * 4 blocks -> ONE wave
#define EPI   32                       // epilogue blocks

#define NEGV (-1000000000.0f)
#define IOU_THR   0.7f
#define SCORE_THR 0.01f

typedef unsigned long long u64;
typedef unsigned int u32;

// scratch
__device__ u64   g_key[NSLICES];       // sortable (value, ~idx) key per slice
__device__ int   g_sel[BN];            // selected original query per slot
__device__ int   g_done  = 0;
__device__ int   g_done2 = 0;

// ---- shared buffer layout (NMS branch only) ----
#define OFF_MASK   0          // u32 [NQ][NWORDS]  = 12000 B
#define OFF_OBOX   12000      // float4[NQ]        = 4800
#define OFF_BX1    16800
#define OFF_BY1    18000
#define OFF_BX2    19200
#define OFF_BY2    20400
#define OFF_OAREA  21600
#define OFF_SCORE  22800
#define OFF_SKEY   24000      // 16B aligned
#define OFF_LABEL  25200
#define OFF_ORDER  26400
#define OFF_VALIDA 27600
#define OFF_VS     27900
#define OFF_RED    28208      // float[32] / keepw u32[10]
#define OFF_MISC   28336      // s_maxc
#define SBUF_SIZE  28352

// monotone map: float bits -> u32 preserving IEEE order (non-NaN)
__device__ __forceinline__ u32 fmap(float f) {
    u32 u = __float_as_uint(f);
    return u ^ ((u32)(((int)u) >> 31) | 0x80000000u);
}

__global__ void __launch_bounds__(TB, 4)
fused_kernel(const float* __restrict__ logits,
             const float* __restrict__ boxes,
             const float* __restrict__ sizes,
             const float* __restrict__ hm,
             const float* __restrict__ off,
             float* __restrict__ out) {
    __shared__ __align__(16) unsigned char sbuf[SBUF_SIZE];
    __shared__ int s_rank;
    const int tid = threadIdx.x;

    if (blockIdx.x >= BATCH) {
        // ---- barrier-free warp-autonomous argmax, cheap reduce -------------
        const int a = blockIdx.x - BATCH;
        const int lane = tid & 31;
        const float4* hm4 = reinterpret_cast<const float4*>(hm);

        int s = a;
        float4 a0, a1, a2, a3;
        {
            const float4* p = hm4 + (size_t)s * (HW / 4);
            a0 = p[tid]; a1 = p[tid + 256]; a2 = p[tid + 512]; a3 = p[tid + 768];
        }

        while (s < NSLICES) {
            // issue next slice's loads first (clamped: unconditional)
            const int s1 = s + ARGB;
            const int s1c = (s1 < NSLICES) ? s1 : (NSLICES - 1);
            float4 b0, b1, b2, b3;
            {
                const float4* p = hm4 + (size_t)s1c * (HW / 4);
                b0 = p[tid]; b1 = p[tid + 256]; b2 = p[tid + 512]; b3 = p[tid + 768];
            }

            // fmax tree (fma pipe, short critical path)
            float m0 = fmaxf(fmaxf(a0.x, a0.y), fmaxf(a0.z, a0.w));
            float m1 = fmaxf(fmaxf(a1.x, a1.y), fmaxf(a1.z, a1.w));
            float m2 = fmaxf(fmaxf(a2.x, a2.y), fmaxf(a2.z, a2.w));
            float m3 = fmaxf(fmaxf(a3.x, a3.y), fmaxf(a3.z, a3.w));
            float M = fmaxf(fmaxf(m0, m1), fmaxf(m2, m3));
#pragma unroll
            for (int o = 16; o > 0; o >>= 1)
                M = fmaxf(M, __shfl_xor_sync(0xFFFFFFFFu, M, o));

            // lowest index equal to M (descending scan => lowest wins)
            u32 bi = 0xFFFFFFFFu;
            const int c0 = tid * 4, c1 = (tid + 256) * 4,
                      c2 = (tid + 512) * 4, c3 = (tid + 768) * 4;
            if (a3.w == M) bi = c3 + 3;
            if (a3.z == M) bi = c3 + 2;
            if (a3.y == M) bi = c3 + 1;
            if (a3.x == M) bi = c3;
            if (a2.w == M) bi = c2 + 3;
            if (a2.z == M) bi = c2 + 2;
            if (a2.y == M) bi = c2 + 1;
            if (a2.x == M) bi = c2;
            if (a1.w == M) bi = c1 + 3;
            if (a1.z == M) bi = c1 + 2;
            if (a1.y == M) bi = c1 + 1;
            if (a1.x == M) bi = c1;
            if (a0.w == M) bi = c0 + 3;
            if (a0.z == M) bi = c0 + 2;
            if (a0.y == M) bi = c0 + 1;
            if (a0.x == M) bi = c0;
            bi = __reduce_min_sync(0xFFFFFFFFu, bi);

            if (lane == 0) {
                u64 key = ((u64)fmap(M) << 32) | (u32)(~bi);
                atomicMax(&g_key[s], key);      // RED.MAX.U64, fire-and-forget
            }

            a0 = b0; a1 = b1; a2 = b2; a3 = b3;
            s = s1;
        }
    } else {
        // ---------------- NMS core: one block per batch ----------------------
        const int b = blockIdx.x;
        unsigned int* mask = (unsigned int*)(sbuf + OFF_MASK);   // [NQ][NWORDS]
        float4* obox  = (float4*)(sbuf + OFF_OBOX);
        float* bx1    = (float*)(sbuf + OFF_BX1);
        float* by1    = (float*)(sbuf + OFF_BY1);
        float* bx2    = (float*)(sbuf + OFF_BX2);
        float* by2    = (float*)(sbuf + OFF_BY2);
        float* oarea  = (float*)(sbuf + OFF_OAREA);
        float* score  = (float*)(sbuf + OFF_SCORE);
        float* skey   = (float*)(sbuf + OFF_SKEY);
        int*   label  = (int*)(sbuf + OFF_LABEL);
        int*   order  = (int*)(sbuf + OFF_ORDER);
        unsigned char* validA = (unsigned char*)(sbuf + OFF_VALIDA);
        unsigned char* vs     = (unsigned char*)(sbuf + OFF_VS);
        float* red    = (float*)(sbuf + OFF_RED);
        unsigned int* keepw = (unsigned int*)(sbuf + OFF_RED);   // reused
        float* s_maxc = (float*)(sbuf + OFF_MISC);

        const float s0 = sizes[b * 2 + 0];
        const float s1 = sizes[b * 2 + 1];

        // --- abs boxes + score/label ---
        float lmax = 0.0f;
        for (int n = tid; n < NQ; n += TB) {
            const float* pb = boxes + ((size_t)b * NQ + n) * 4;
            float cx = pb[0], cy = pb[1], w = pb[2], h = pb[3];
            float x1 = (cx - w / 2.0f) * s0;
            float y1 = (cy - h / 2.0f) * s1;
            float x2 = (cx + w / 2.0f) * s0;
            float y2 = (cy + h / 2.0f) * s1;
            bx1[n] = x1; by1[n] = y1; bx2[n] = x2; by2[n] = y2;
            lmax = fmaxf(lmax, fmaxf(fmaxf(fabsf(x1), fabsf(y1)),
                                     fmaxf(fabsf(x2), fabsf(y2))));
            const float4* pl4 = reinterpret_cast<const float4*>(
                logits + ((size_t)b * NQ + n) * NC);
            float bestv = -INFINITY;
            int   bl = 0;
#pragma unroll 4
            for (int c4 = 0; c4 < NC / 4; c4++) {
                float4 v = pl4[c4];
                int c = c4 * 4;
                if (v.x > bestv) { bestv = v.x; bl = c; }
                if (v.y > bestv) { bestv = v.y; bl = c + 1; }
                if (v.z > bestv) { bestv = v.z; bl = c + 2; }
                if (v.w > bestv) { bestv = v.w; bl = c + 3; }
            }
            float sc = 1.0f / (1.0f + expf(-bestv));
            score[n]  = sc;
            label[n]  = bl;
            bool valid = sc > SCORE_THR;
            validA[n] = valid ? 1 : 0;
            skey[n]   = valid ? sc : NEGV;
        }
#pragma unroll
        for (int o = 16; o > 0; o >>= 1)
            lmax = fmaxf(lmax, __shfl_down_sync(0xFFFFFFFFu, lmax, o));
        if ((tid & 31) == 0) red[tid >> 5] = lmax;
        __syncthreads();
        if (tid == 0) {
            float m = red[0];
#pragma unroll
            for (int w = 1; w < 8; w++) m = fmaxf(m, red[w]);
            *s_maxc = m + 1.0f;
        }
        __syncthreads();
        const float maxc = *s_maxc;

        // --- stable descending rank sort (== jnp.argsort(-s)) ---
        for (int i = tid; i < NQ; i += TB) {
            float si = skey[i];
            int r = 0;
            const float4* sk4 = reinterpret_cast<const float4*>(skey);
#pragma unroll 5
            for (int j4 = 0; j4 < NQ / 4; j4++) {
                float4 v = sk4[j4];
                int j = j4 * 4;
                r += (v.x > si) || (v.x == si && (j    ) < i);
                r += (v.y > si) || (v.y == si && (j + 1) < i);
                r += (v.z > si) || (v.z == si && (j + 2) < i);
                r += (v.w > si) || (v.w == si && (j + 3) < i);
            }
            order[r] = i;
        }
        __syncthreads();

        // --- sorted class-offset boxes ---
        for (int r = tid; r < NQ; r += TB) {
            int i = order[r];
            float o = (float)label[i] * maxc;
            float x1 = bx1[i] + o, y1 = by1[i] + o;
            float x2 = bx2[i] + o, y2 = by2[i] + o;
            obox[r] = make_float4(x1, y1, x2, y2);
            oarea[r] = (x2 - x1) * (y2 - y1);
            vs[r] = validA[i];
        }
        __syncthreads();

        // --- IoU bitmask, w-major: warp lanes share w -> broadcast LDS ---
        for (int u = tid; u < NQ * NWORDS; u += TB) {
            int i = u % NQ;
            int w = u / NQ;
            int j0 = w * 32;
            unsigned int bits = 0;
            if (j0 + 31 > i) {
                float4 bi4 = obox[i];
                float ai = oarea[i];
                int jend = (NQ - j0 < 32) ? (NQ - j0) : 32;
                for (int jj = 0; jj < jend; jj++) {
                    int j = j0 + jj;
                    if (j > i) {
                        float4 bj = obox[j];
                        float iw = fmaxf(fminf(bi4.z, bj.z) - fmaxf(bi4.x, bj.x), 0.0f);
                        float ih = fmaxf(fminf(bi4.w, bj.w) - fmaxf(bi4.y, bj.y), 0.0f);
                        float inter = iw * ih;
                        if (inter > 0.0f) {        // inter==0 -> iou==0 (exact)
                            float iou = inter / (ai + oarea[j] - inter + 1e-9f);
                            if (iou > IOU_THR) bits |= (1u << jj);
                        }
                    }
                }
            }
            mask[i * NWORDS + w] = bits;
        }
        __syncthreads();

        // --- greedy pass: warp 0, lane w owns suppression word w ---
        if (tid < 32) {
            const int lane = tid;
            unsigned int supp_w = 0, kw_w = 0;
            for (int i = 0; i < NQ; i++) {
                unsigned int sw = __shfl_sync(0xFFFFFFFFu, supp_w, i >> 5);
                unsigned int k = (unsigned int)vs[i] & (((sw >> (i & 31)) & 1u) ^ 1u);
                if (lane == (i >> 5)) kw_w |= k << (i & 31);
                unsigned int m = 0u - k;
                if (lane < NWORDS) supp_w |= mask[i * NWORDS + lane] & m;
            }
            if (lane < NWORDS) keepw[lane] = kw_w;
        }
        __syncthreads();

        // --- stable partition via popcount + write fl/fb/fs/vk, stash g_sel ---
        const int base = b * NQ;
        float* fl = out;
        float* fb = out + BN;
        float* fs = out + BN * 5;
        float* vk = out + BN * 6 + BN * NK * 3;

        for (int r = tid; r < NQ; r += TB) {
            int wq = r >> 5, bq = r & 31;
            int kb = 0, nk = 0;
#pragma unroll
            for (int w = 0; w < NWORDS; w++) {
                unsigned int kwv = keepw[w];
                nk += __popc(kwv);
                if (w < wq)  kb += __popc(kwv);
                if (w == wq) kb += __popc(kwv & ((1u << bq) - 1u));
            }
            bool kf = (keepw[wq] >> bq) & 1u;
            int m = kf ? kb : (nk + (r - kb));
            int q = order[r];
            g_sel[base + m] = q;
            vk[base + m] = kf ? 1.0f : 0.0f;
            fl[base + m] = kf ? (float)label[q] : -1.0f;
            fs[base + m] = kf ? score[q] : 0.0f;
            float* pb = fb + (size_t)(base + m) * 4;
            pb[0] = kf ? bx1[q] : 0.0f;
            pb[1] = kf ? by1[q] : 0.0f;
            pb[2] = kf ? bx2[q] : 0.0f;
            pb[3] = kf ? by2[q] : 0.0f;
        }
    }

    // ------------- distributed last-EPI-blocks epilogue: keypoint gather -----
    __threadfence();
    __syncthreads();
    if (tid == 0) s_rank = atomicAdd(&g_done, 1);
    __syncthreads();
    const int rank = s_rank;
    if (rank >= GRID_TOTAL - EPI) {
        if (tid == 0) {
            while (atomicAdd(&g_done, 0) < GRID_TOTAL) {}
        }
        __syncthreads();
        __threadfence();
        float* ak = out + BN * 6;
        const float* vk = out + BN * 6 + BN * NK * 3;
        const float* fb = out + BN;
        const float2* off2 = reinterpret_cast<const float2*>(off);
        const int er = rank - (GRID_TOTAL - EPI);
        for (int idx = er * TB + tid; idx < NSLICES; idx += EPI * TB) {
            int k  = idx % NK;
            int bm = idx / NK;                 // b*NQ + m
            float* o = ak + (size_t)idx * 3;
            if (vk[bm] != 0.0f) {
                int bq = bm / NQ;
                int q = g_sel[bm];
                const int slice = (bq * NQ + q) * NK + k;
                u64 key = g_key[slice];
                int bi = (int)(~((u32)key)) & (HW - 1);
                u32 mapped = (u32)(key >> 32);
                u32 ubits = (mapped & 0x80000000u) ? (mapped ^ 0x80000000u)
                                                   : ~mapped;
                float M = __uint_as_float(ubits);
                float2 ov = off2[slice];
                float nx = (float)(bi & 63) / 63.0f + ov.x;
                float ny = (float)(bi >> 6) / 63.0f + ov.y;
                nx = fminf(fmaxf(nx, 0.0f), 1.0f);
                ny = fminf(fmaxf(ny, 0.0f), 1.0f);
                const float* pb = fb + (size_t)bm * 4;
                float x1 = pb[0], y1 = pb[1], x2 = pb[2], y2 = pb[3];
                o[0] = x1 + nx * (x2 - x1);
                o[1] = y1 + ny * (y2 - y1);
                o[2] = M;
            } else {
                o[0] = 0.0f; o[1] = 0.0f; o[2] = 0.0f;
            }
        }
        __threadfence();
        __syncthreads();
        if (tid == 0) {
            int o2 = atomicAdd(&g_done2, 1);
            if (o2 == EPI - 1) { g_done = 0; g_done2 = 0; }   // reset for replay
        }
    }
}

// ---------------------------------------------------------------------------
extern "C" void kernel_launch(void* const* d_in, const int* in_sizes, int n_in,
                              void* d_out, int out_size) {
    const float* logits = (const float*)d_in[0];   // (4,300,80)
    const float* boxes  = (const float*)d_in[1];   // (4,300,4)
    const float* hm     = (const float*)d_in[2];   // (4,300,17,64,64)
    const float* off    = (const float*)d_in[3];   // (4,300,17,2)
    const float* sizes  = (const float*)d_in[4];   // (4,2)
    float* out = (float*)d_out;

    fused_kernel<<<GRID_TOTAL, TB>>>(logits, boxes, sizes, hm, off, out);
}

// round 15
// speedup vs baseline: 1.1211x; 1.0985x over previous
#include <cuda_runtime.h>
#include <math.h>

#define BATCH 4
#define NQ    300
#define NC    80
#define NK    17
#define HW    4096
#define NWORDS 10                      // ceil(300/32)
#define BN    (BATCH*NQ)
#define TB    512
#define NSLICES (BATCH*NQ*NK)          // 20400
#define ARGB  440                      // persistent argmax blocks
#define GRID_TOTAL (BATCH + ARGB)      // 444 = 148 SMs * 3 blocks -> ONE wave
#define EPI   32                       // epilogue blocks

#define NEGV (-1000000000.0f)
#define IOU_THR   0.7f
#define SCORE_THR 0.01f

typedef unsigned long long u64;
typedef unsigned int u32;

// scratch
__device__ u64   g_key[NSLICES];       // sortable (value, ~idx) key per slice
__device__ int   g_sel[BN];            // selected original query per slot
__device__ int   g_done  = 0;
__device__ int   g_done2 = 0;

// ---- shared buffer layout (NMS branch only) ----
#define OFF_MASK   0          // u32 [NQ][NWORDS]  = 12000 B
#define OFF_OBOX   12000      // float4[NQ]        = 4800
#define OFF_BX1    16800
#define OFF_BY1    18000
#define OFF_BX2    19200
#define OFF_BY2    20400
#define OFF_OAREA  21600
#define OFF_SCORE  22800
#define OFF_SKEY   24000      // 16B aligned
#define OFF_LABEL  25200
#define OFF_ORDER  26400
#define OFF_VALIDA 27600
#define OFF_VS     27900
#define OFF_RED    28208      // float[32] / keepw u32[10]
#define OFF_MISC   28336      // s_maxc
#define SBUF_SIZE  28352

// monotone map: float bits -> u32 preserving IEEE order (non-NaN)
__device__ __forceinline__ u32 fmap(float f) {
    u32 u = __float_as_uint(f);
    return u ^ ((u32)(((int)u) >> 31) | 0x80000000u);
}

__global__ void __launch_bounds__(TB, 3)
fused_kernel(const float* __restrict__ logits,
             const float* __restrict__ boxes,
             const float* __restrict__ sizes,
             const float* __restrict__ hm,
             const float* __restrict__ off,
             float* __restrict__ out) {
    __shared__ __align__(16) unsigned char sbuf[SBUF_SIZE];
    __shared__ int s_rank;
    const int tid = threadIdx.x;

    if (blockIdx.x >= BATCH) {
        // ---- barrier-free argmax: 512 thr/block, 8 elems/thread, prefetch --
        const int a = blockIdx.x - BATCH;
        const int lane = tid & 31;
        const float4* hm4 = reinterpret_cast<const float4*>(hm);

        int s = a;
        float4 a0, a1;
        {
            const float4* p = hm4 + (size_t)s * (HW / 4);
            a0 = p[tid]; a1 = p[tid + 512];
        }

        while (s < NSLICES) {
            // issue next slice's loads first (clamped: unconditional)
            const int s1 = s + ARGB;
            const int s1c = (s1 < NSLICES) ? s1 : (NSLICES - 1);
            float4 b0, b1;
            {
                const float4* p = hm4 + (size_t)s1c * (HW / 4);
                b0 = p[tid]; b1 = p[tid + 512];
            }

            // fmax tree over 8 held elements
            float m0 = fmaxf(fmaxf(a0.x, a0.y), fmaxf(a0.z, a0.w));
            float m1 = fmaxf(fmaxf(a1.x, a1.y), fmaxf(a1.z, a1.w));
            float M = fmaxf(m0, m1);
#pragma unroll
            for (int o = 16; o > 0; o >>= 1)
                M = fmaxf(M, __shfl_xor_sync(0xFFFFFFFFu, M, o));

            // lowest index equal to M (descending scan => lowest wins)
            u32 bi = 0xFFFFFFFFu;
            const int c0 = tid * 4, c1 = (tid + 512) * 4;
            if (a1.w == M) bi = c1 + 3;
            if (a1.z == M) bi = c1 + 2;
            if (a1.y == M) bi = c1 + 1;
            if (a1.x == M) bi = c1;
            if (a0.w == M) bi = c0 + 3;
            if (a0.z == M) bi = c0 + 2;
            if (a0.y == M) bi = c0 + 1;
            if (a0.x == M) bi = c0;
            bi = __reduce_min_sync(0xFFFFFFFFu, bi);

            if (lane == 0) {
                u64 key = ((u64)fmap(M) << 32) | (u32)(~bi);
                atomicMax(&g_key[s], key);      // RED.MAX.U64, fire-and-forget
            }

            a0 = b0; a1 = b1;
            s = s1;
        }
    } else {
        // ---------------- NMS core: one block per batch ----------------------
        const int b = blockIdx.x;
        unsigned int* mask = (unsigned int*)(sbuf + OFF_MASK);   // [NQ][NWORDS]
        float4* obox  = (float4*)(sbuf + OFF_OBOX);
        float* bx1    = (float*)(sbuf + OFF_BX1);
        float* by1    = (float*)(sbuf + OFF_BY1);
        float* bx2    = (float*)(sbuf + OFF_BX2);
        float* by2    = (float*)(sbuf + OFF_BY2);
        float* oarea  = (float*)(sbuf + OFF_OAREA);
        float* score  = (float*)(sbuf + OFF_SCORE);
        float* skey   = (float*)(sbuf + OFF_SKEY);
        int*   label  = (int*)(sbuf + OFF_LABEL);
        int*   order  = (int*)(sbuf + OFF_ORDER);
        unsigned char* validA = (unsigned char*)(sbuf + OFF_VALIDA);
        unsigned char* vs     = (unsigned char*)(sbuf + OFF_VS);
        float* red    = (float*)(sbuf + OFF_RED);
        unsigned int* keepw = (unsigned int*)(sbuf + OFF_RED);   // reused
        float* s_maxc = (float*)(sbuf + OFF_MISC);

        const float s0 = sizes[b * 2 + 0];
        const float s1 = sizes[b * 2 + 1];

        // --- abs boxes + score/label ---
        float lmax = 0.0f;
        for (int n = tid; n < NQ; n += TB) {
            const float* pb = boxes + ((size_t)b * NQ + n) * 4;
            float cx = pb[0], cy = pb[1], w = pb[2], h = pb[3];
            float x1 = (cx - w / 2.0f) * s0;
            float y1 = (cy - h / 2.0f) * s1;
            float x2 = (cx + w / 2.0f) * s0;
            float y2 = (cy + h / 2.0f) * s1;
            bx1[n] = x1; by1[n] = y1; bx2[n] = x2; by2[n] = y2;
            lmax = fmaxf(lmax, fmaxf(fmaxf(fabsf(x1), fabsf(y1)),
                                     fmaxf(fabsf(x2), fabsf(y2))));
            const float4* pl4 = reinterpret_cast<const float4*>(
                logits + ((size_t)b * NQ + n) * NC);
            float bestv = -INFINITY;
            int   bl = 0;
#pragma unroll 4
            for (int c4 = 0; c4 < NC / 4; c4++) {
                float4 v = pl4[c4];
                int c = c4 * 4;
                if (v.x > bestv) { bestv = v.x; bl = c; }
                if (v.y > bestv) { bestv = v.y; bl = c + 1; }
                if (v.z > bestv) { bestv = v.z; bl = c + 2; }
                if (v.w > bestv) { bestv = v.w; bl = c + 3; }
            }
            float sc = 1.0f / (1.0f + expf(-bestv));
            score[n]  = sc;
            label[n]  = bl;
            bool valid = sc > SCORE_THR;
            validA[n] = valid ? 1 : 0;
            skey[n]   = valid ? sc : NEGV;
        }
#pragma unroll
        for (int o = 16; o > 0; o >>= 1)
            lmax = fmaxf(lmax, __shfl_down_sync(0xFFFFFFFFu, lmax, o));
        if ((tid & 31) == 0) red[tid >> 5] = lmax;
        __syncthreads();
        if (tid == 0) {
            float m = red[0];
#pragma unroll
            for (int w = 1; w < 16; w++) m = fmaxf(m, red[w]);
            *s_maxc = m + 1.0f;
        }
        __syncthreads();
        const float maxc = *s_maxc;

        // --- stable descending rank sort (== jnp.argsort(-s)) ---
        for (int i = tid; i < NQ; i += TB) {
            float si = skey[i];
            int r = 0;
            const float4* sk4 = reinterpret_cast<const float4*>(skey);
#pragma unroll 5
            for (int j4 = 0; j4 < NQ / 4; j4++) {
                float4 v = sk4[j4];
                int j = j4 * 4;
                r += (v.x > si) || (v.x == si && (j    ) < i);
                r += (v.y > si) || (v.y == si && (j + 1) < i);
                r += (v.z > si) || (v.z == si && (j + 2) < i);
                r += (v.w > si) || (v.w == si && (j + 3) < i);
            }
            order[r] = i;
        }
        __syncthreads();

        // --- sorted class-offset boxes ---
        for (int r = tid; r < NQ; r += TB) {
            int i = order[r];
            float o = (float)label[i] * maxc;
            float x1 = bx1[i] + o, y1 = by1[i] + o;
            float x2 = bx2[i] + o, y2 = by2[i] + o;
            obox[r] = make_float4(x1, y1, x2, y2);
            oarea[r] = (x2 - x1) * (y2 - y1);
            vs[r] = validA[i];
        }
        __syncthreads();

        // --- IoU bitmask, w-major: warp lanes share w -> broadcast LDS ---
        for (int u = tid; u < NQ * NWORDS; u += TB) {
            int i = u % NQ;
            int w = u / NQ;
            int j0 = w * 32;
            unsigned int bits = 0;
            if (j0 + 31 > i) {
                float4 bi4 = obox[i];
                float ai = oarea[i];
                int jend = (NQ - j0 < 32) ? (NQ - j0) : 32;
                for (int jj = 0; jj < jend; jj++) {
                    int j = j0 + jj;
                    if (j > i) {
                        float4 bj = obox[j];
                        float iw = fmaxf(fminf(bi4.z, bj.z) - fmaxf(bi4.x, bj.x), 0.0f);
                        float ih = fmaxf(fminf(bi4.w, bj.w) - fmaxf(bi4.y, bj.y), 0.0f);
                        float inter = iw * ih;
                        if (inter > 0.0f) {        // inter==0 -> iou==0 (exact)
                            float iou = inter / (ai + oarea[j] - inter + 1e-9f);
                            if (iou > IOU_THR) bits |= (1u << jj);
                        }
                    }
                }
            }
            mask[i * NWORDS + w] = bits;
        }
        __syncthreads();

        // --- greedy pass: warp 0, lane w owns suppression word w ---
        if (tid < 32) {
            const int lane = tid;
            unsigned int supp_w = 0, kw_w = 0;
            for (int i = 0; i < NQ; i++) {
                unsigned int sw = __shfl_sync(0xFFFFFFFFu, supp_w, i >> 5);
                unsigned int k = (unsigned int)vs[i] & (((sw >> (i & 31)) & 1u) ^ 1u);
                if (lane == (i >> 5)) kw_w |= k << (i & 31);
                unsigned int m = 0u - k;
                if (lane < NWORDS) supp_w |= mask[i * NWORDS + lane] & m;
            }
            if (lane < NWORDS) keepw[lane] = kw_w;
        }
        __syncthreads();

        // --- stable partition via popcount + write fl/fb/fs/vk, stash g_sel ---
        const int base = b * NQ;
        float* fl = out;
        float* fb = out + BN;
        float* fs = out + BN * 5;
        float* vk = out + BN * 6 + BN * NK * 3;

        for (int r = tid; r < NQ; r += TB) {
            int wq = r >> 5, bq = r & 31;
            int kb = 0, nk = 0;
#pragma unroll
            for (int w = 0; w < NWORDS; w++) {
                unsigned int kwv = keepw[w];
                nk += __popc(kwv);
                if (w < wq)  kb += __popc(kwv);
                if (w == wq) kb += __popc(kwv & ((1u << bq) - 1u));
            }
            bool kf = (keepw[wq] >> bq) & 1u;
            int m = kf ? kb : (nk + (r - kb));
            int q = order[r];
            g_sel[base + m] = q;
            vk[base + m] = kf ? 1.0f : 0.0f;
            fl[base + m] = kf ? (float)label[q] : -1.0f;
            fs[base + m] = kf ? score[q] : 0.0f;
            float* pb = fb + (size_t)(base + m) * 4;
            pb[0] = kf ? bx1[q] : 0.0f;
            pb[1] = kf ? by1[q] : 0.0f;
            pb[2] = kf ? bx2[q] : 0.0f;
            pb[3] = kf ? by2[q] : 0.0f;
        }
    }

    // ------------- distributed last-EPI-blocks epilogue: keypoint gather -----
    __threadfence();
    __syncthreads();
    if (tid == 0) s_rank = atomicAdd(&g_done, 1);
    __syncthreads();
    const int rank = s_rank;
    if (rank >= GRID_TOTAL - EPI) {
        if (tid == 0) {
            while (atomicAdd(&g_done, 0) < GRID_TOTAL) {}
        }
        __syncthreads();
        __threadfence();
        float* ak = out + BN * 6;
        const float* vk = out + BN * 6 + BN * NK * 3;
        const float* fb = out + BN;
        const float2* off2 = reinterpret_cast<const float2*>(off);
        const int er = rank - (GRID_TOTAL - EPI);
        for (int idx = er * TB + tid; idx < NSLICES; idx += EPI * TB) {
            int k  = idx % NK;
            int bm = idx / NK;                 // b*NQ + m
            float* o = ak + (size_t)idx * 3;
            if (vk[bm] != 0.0f) {
                int bq = bm / NQ;
                int q = g_sel[bm];
                const int slice = (bq * NQ + q) * NK + k;
                u64 key = g_key[slice];
                int bi = (int)(~((u32)key)) & (HW - 1);
                u32 mapped = (u32)(key >> 32);
                u32 ubits = (mapped & 0x80000000u) ? (mapped ^ 0x80000000u)
                                                   : ~mapped;
                float M = __uint_as_float(ubits);
                float2 ov = off2[slice];
                float nx = (float)(bi & 63) / 63.0f + ov.x;
                float ny = (float)(bi >> 6) / 63.0f + ov.y;
                nx = fminf(fmaxf(nx, 0.0f), 1.0f);
                ny = fminf(fmaxf(ny, 0.0f), 1.0f);
                const float* pb = fb + (size_t)bm * 4;
                float x1 = pb[0], y1 = pb[1], x2 = pb[2], y2 = pb[3];
                o[0] = x1 + nx * (x2 - x1);
                o[1] = y1 + ny * (y2 - y1);
                o[2] = M;
            } else {
                o[0] = 0.0f; o[1] = 0.0f; o[2] = 0.0f;
            }
        }
        __threadfence();
        __syncthreads();
        if (tid == 0) {
            int o2 = atomicAdd(&g_done2, 1);
            if (o2 == EPI - 1) { g_done = 0; g_done2 = 0; }   // reset for replay
        }
    }
}

// ---------------------------------------------------------------------------
extern "C" void kernel_launch(void* const* d_in, const int* in_sizes, int n_in,
                              void* d_out, int out_size) {
    const float* logits = (const float*)d_in[0];   // (4,300,80)
    const float* boxes  = (const float*)d_in[1];   // (4,300,4)
    const float* hm     = (const float*)d_in[2];   // (4,300,17,64,64)
    const float* off    = (const float*)d_in[3];   // (4,300,17,2)
    const float* sizes  = (const float*)d_in[4];   // (4,2)
    float* out = (float*)d_out;

    fused_kernel<<<GRID_TOTAL, TB>>>(logits, boxes, sizes, hm, off, out);
}